// round 12
// baseline (speedup 1.0000x reference)
#include <cuda_runtime.h>
#include <cuda_bf16.h>
#include <cstdint>

namespace {
constexpr int Sd = 2048, Dd = 64, QT = 64, CH = 64, NCH = Sd / CH, NT = 256;
constexpr int PIT = 72;                      // bf16 row pitch (conflict-free LDSM)
constexpr int TILE = QT * PIT * 2;           // 9216 bytes per bf16 tile

// K_a smem: Q hi/lo + K 2bufs x (hi+lo)
constexpr int A_SQH = 0, A_SQL = TILE, A_SK = 2 * TILE;
constexpr int A_SMEM = 6 * TILE;             // 55296
// K_b smem: P 2bufs x (hi+lo) + V 2bufs x (hi+lo) + sinv
constexpr int B_SP = 0, B_SV = 4 * TILE, B_SINV = 8 * TILE;
constexpr int B_SMEM = 8 * TILE + 256;       // 73984

__device__ float g_inv[65536];
// bf16 hi/lo K,V copies (8MB each) and P planes (256MB each).
__device__ __nv_bfloat16 g_KH[2 * 16 * 2048 * 64];
__device__ __nv_bfloat16 g_KL[2 * 16 * 2048 * 64];
__device__ __nv_bfloat16 g_VH[2 * 16 * 2048 * 64];
__device__ __nv_bfloat16 g_VL[2 * 16 * 2048 * 64];
__device__ __nv_bfloat16 g_Ph[(size_t)32 * 2048 * 2048];
__device__ __nv_bfloat16 g_Pl[(size_t)32 * 2048 * 2048];

__device__ __forceinline__ uint32_t smem_u32(const void* p) {
    uint32_t a;
    asm("{ .reg .u64 t; cvta.to.shared.u64 t, %1; cvt.u32.u64 %0, t; }"
        : "=r"(a) : "l"(p));
    return a;
}
__device__ __forceinline__ uint32_t pack2(float a, float b) {  // lo=a, hi=b
    uint32_t r;
    asm("cvt.rn.bf16x2.f32 %0, %1, %2;" : "=r"(r) : "f"(b), "f"(a));
    return r;
}
__device__ __forceinline__ float bfr(float x) {
    return __bfloat162float(__float2bfloat16(x));
}
__device__ __forceinline__ void ldm_x4(uint32_t a, uint32_t* r) {
    asm volatile("ldmatrix.sync.aligned.m8n8.x4.shared.b16 {%0,%1,%2,%3}, [%4];"
                 : "=r"(r[0]), "=r"(r[1]), "=r"(r[2]), "=r"(r[3]) : "r"(a));
}
__device__ __forceinline__ void ldm_x2(uint32_t a, uint32_t* r) {
    asm volatile("ldmatrix.sync.aligned.m8n8.x2.shared.b16 {%0,%1}, [%2];"
                 : "=r"(r[0]), "=r"(r[1]) : "r"(a));
}
__device__ __forceinline__ void ldm_x2t(uint32_t a, uint32_t* r) {
    asm volatile("ldmatrix.sync.aligned.m8n8.x2.trans.shared.b16 {%0,%1}, [%2];"
                 : "=r"(r[0]), "=r"(r[1]) : "r"(a));
}
__device__ __forceinline__ void mma_bf16(float* d, const uint32_t* a,
                                         const uint32_t* b) {
    asm volatile(
        "mma.sync.aligned.m16n8k16.row.col.f32.bf16.bf16.f32 "
        "{%0,%1,%2,%3}, {%4,%5,%6,%7}, {%8,%9}, {%0,%1,%2,%3};"
        : "+f"(d[0]), "+f"(d[1]), "+f"(d[2]), "+f"(d[3])
        : "r"(a[0]), "r"(a[1]), "r"(a[2]), "r"(a[3]), "r"(b[0]), "r"(b[1]));
}
__device__ __forceinline__ void cpa16(uint32_t dst, const void* src) {
    asm volatile("cp.async.cg.shared.global [%0], [%1], 16;"
                 :: "r"(dst), "l"(src));
}
__device__ __forceinline__ void cpa_commit() {
    asm volatile("cp.async.commit_group;" ::: "memory");
}
__device__ __forceinline__ void cpa_wait0() {
    asm volatile("cp.async.wait_group 0;" ::: "memory");
}
// u32 with bf16 in low16 / high16 -> floats
__device__ __forceinline__ float lo16f(uint32_t u) {
    return __uint_as_float(u << 16);
}
__device__ __forceinline__ float hi16f(uint32_t u) {
    return __uint_as_float(u & 0xffff0000u);
}
} // namespace

// ---------------- prepass: fp32 K/V -> bf16 hi/lo scratch -------------------
__global__ void __launch_bounds__(256, 8)
conv_kv_kernel(const float* __restrict__ K, const float* __restrict__ V)
{
    const size_t i4 = (size_t)blockIdx.x * 256 + threadIdx.x;
    const float4 kv = *(const float4*)(K + i4 * 4);
    const float4 vv = *(const float4*)(V + i4 * 4);
    const float khx = bfr(kv.x), khy = bfr(kv.y), khz = bfr(kv.z), khw = bfr(kv.w);
    const float vhx = bfr(vv.x), vhy = bfr(vv.y), vhz = bfr(vv.z), vhw = bfr(vv.w);
    ((uint2*)g_KH)[i4] = make_uint2(pack2(kv.x, kv.y), pack2(kv.z, kv.w));
    ((uint2*)g_KL)[i4] =
        make_uint2(pack2(kv.x - khx, kv.y - khy), pack2(kv.z - khz, kv.w - khw));
    ((uint2*)g_VH)[i4] = make_uint2(pack2(vv.x, vv.y), pack2(vv.z, vv.w));
    ((uint2*)g_VL)[i4] =
        make_uint2(pack2(vv.x - vhx, vv.y - vhy), pack2(vv.z - vhz, vv.w - vhw));
}

// ============================ K_a: QK + exp -> P planes =====================
__global__ void __launch_bounds__(NT, 2)
attn_qk_kernel(const float* __restrict__ Q, const float* __restrict__ Mk)
{
    extern __shared__ char smem[];
    const uint32_t sb = smem_u32(smem);

    const int t = threadIdx.x, w = t >> 5, l = t & 31;
    const int qw = w & 3, kh = w >> 2;
    const int gid = l >> 2, qd = l & 3;
    const int qt = blockIdx.x, bh = blockIdx.y;

    const float* Qb = Q + ((long)bh * Sd + qt * QT) * Dd;
    const float* Mb = Mk + ((long)bh * Sd + qt * QT) * Sd;
    const __nv_bfloat16* KHb = g_KH + (long)bh * Sd * Dd;
    const __nv_bfloat16* KLb = g_KL + (long)bh * Sd * Dd;

    auto stage_k = [&](int c, int buf) {
        const long srow = (long)c * CH * Dd;
        const uint32_t kb = sb + A_SK + buf * 2 * TILE;
        #pragma unroll
        for (int half = 0; half < 2; ++half) {
            const int g = t + half * 256;
            const int r = g >> 3, u = g & 7;
            const long so = srow + r * Dd + u * 8;
            const uint32_t dofs = (uint32_t)((r * PIT + u * 8) * 2);
            cpa16(kb + dofs, KHb + so);
            cpa16(kb + TILE + dofs, KLb + so);
        }
    };

    stage_k(0, 0);
    cpa_commit();
    // Q convert (x 1/8)
    #pragma unroll
    for (int i = 0; i < 4; ++i) {
        const int idx4 = t + NT * i;
        const int row = idx4 >> 4, c4 = (idx4 & 15) << 2;
        float4 v = *(const float4*)(Qb + (size_t)idx4 * 4);
        v.x *= 0.125f; v.y *= 0.125f; v.z *= 0.125f; v.w *= 0.125f;
        const float hx = bfr(v.x), hy = bfr(v.y), hz = bfr(v.z), hw = bfr(v.w);
        const int boff = (row * PIT + c4) * 2;
        *(uint2*)(smem + A_SQH + boff) =
            make_uint2(pack2(v.x, v.y), pack2(v.z, v.w));
        *(uint2*)(smem + A_SQL + boff) =
            make_uint2(pack2(v.x - hx, v.y - hy), pack2(v.z - hz, v.w - hw));
    }
    cpa_wait0();
    __syncthreads();

    uint32_t qh[4][4], ql[4][4];
    {
        const int rowb = ((16 * qw + (l & 15)) * PIT + ((l >> 4) << 3)) * 2;
        #pragma unroll
        for (int kt = 0; kt < 4; ++kt) {
            ldm_x4(sb + A_SQH + rowb + kt * 32, qh[kt]);
            ldm_x4(sb + A_SQL + rowb + kt * 32, ql[kt]);
        }
    }

    float rs0 = 0.f, rs1 = 0.f;
    const int l2 = l & 15;
    const int koff = ((l2 & 7) * PIT + ((l2 >> 3) << 3)) * 2;
    const float* mrow = Mb + (long)(16 * qw + gid) * Sd + kh * 32 + 2 * qd;

    // P plane u32 indices (2 bf16 per u32).
    uint32_t* PhU = (uint32_t*)g_Ph;
    uint32_t* PlU = (uint32_t*)g_Pl;
    const size_t prow0 =
        ((size_t)bh * Sd + qt * QT + 16 * qw + gid) * (Sd / 2) + kh * 16 + qd;
    const size_t prow8 = prow0 + 8 * (Sd / 2);

    for (int c = 0; c < NCH; ++c) {
        const int buf = c & 1;
        if (c + 1 < NCH) { stage_k(c + 1, buf ^ 1); cpa_commit(); }

        const int cb = c * CH;
        float2 mk0[4], mk1[4];
        #pragma unroll
        for (int nt = 0; nt < 4; ++nt) {
            mk0[nt] = *(const float2*)(mrow + cb + nt * 8);
            mk1[nt] = *(const float2*)(mrow + cb + nt * 8 + 8 * (long)Sd);
        }

        const uint32_t kh_base = sb + A_SK + buf * 2 * TILE + koff;
        const uint32_t kl_base = kh_base + TILE;

        #pragma unroll
        for (int nt = 0; nt < 4; ++nt) {
            const int ntg = kh * 4 + nt;
            float sA[4] = {0.f,0.f,0.f,0.f};
            float sB[4] = {0.f,0.f,0.f,0.f};
            float sC[4] = {0.f,0.f,0.f,0.f};
            #pragma unroll
            for (int kt = 0; kt < 4; ++kt) {
                const uint32_t off = (uint32_t)(ntg * 8 * PIT * 2 + kt * 32);
                uint32_t kfh[2], kfl[2];
                ldm_x2(kh_base + off, kfh);
                ldm_x2(kl_base + off, kfl);
                mma_bf16(sA, qh[kt], kfh);
                mma_bf16(sB, qh[kt], kfl);
                mma_bf16(sC, ql[kt], kfh);
            }
            const float e0 = __expf((sA[0] + sB[0]) + (sC[0] + mk0[nt].x));
            const float e1 = __expf((sA[1] + sB[1]) + (sC[1] + mk0[nt].y));
            const float e2 = __expf((sA[2] + sB[2]) + (sC[2] + mk1[nt].x));
            const float e3 = __expf((sA[3] + sB[3]) + (sC[3] + mk1[nt].y));
            rs0 += e0 + e1; rs1 += e2 + e3;
            const size_t ci = (size_t)c * 32 + nt * 4;
            PhU[prow0 + ci] = pack2(e0, e1);
            PhU[prow8 + ci] = pack2(e2, e3);
            PlU[prow0 + ci] = pack2(e0 - bfr(e0), e1 - bfr(e1));
            PlU[prow8 + ci] = pack2(e2 - bfr(e2), e3 - bfr(e3));
        }
        if (c + 1 < NCH) cpa_wait0();
        __syncthreads();
    }

    #pragma unroll
    for (int o = 1; o < 4; o <<= 1) {
        rs0 += __shfl_xor_sync(0xffffffffu, rs0, o);
        rs1 += __shfl_xor_sync(0xffffffffu, rs1, o);
    }
    float* srs = (float*)smem;
    if (qd == 0) {
        srs[kh * 64 + 16 * qw + gid]     = rs0;
        srs[kh * 64 + 16 * qw + gid + 8] = rs1;
    }
    __syncthreads();
    if (qd == 0 && kh == 0) {
        const int r0 = 16 * qw + gid;
        const int grow = bh * Sd + qt * QT + r0;
        g_inv[grow]     = 1.0f / (srs[r0] + srs[64 + r0]);
        g_inv[grow + 8] = 1.0f / (srs[r0 + 8] + srs[64 + r0 + 8]);
    }
}

// =============== K_b: PV + normalized attention from fragments ==============
__global__ void __launch_bounds__(NT, 2)
attn_pv_kernel(float* __restrict__ OC, float* __restrict__ OA)
{
    extern __shared__ char smem[];
    const uint32_t sb = smem_u32(smem);
    float* sinv = (float*)(smem + B_SINV);

    const int t = threadIdx.x, w = t >> 5, l = t & 31;
    const int qw = w & 3, kh = w >> 2;
    const int gid = l >> 2, qd = l & 3;
    const int qt = blockIdx.x, bh = blockIdx.y;

    const __nv_bfloat16* VHb = g_VH + (long)bh * Sd * Dd;
    const __nv_bfloat16* VLb = g_VL + (long)bh * Sd * Dd;
    const __nv_bfloat16* PHb = g_Ph + ((size_t)bh * Sd + qt * QT) * Sd;
    const __nv_bfloat16* PLb = g_Pl + ((size_t)bh * Sd + qt * QT) * Sd;
    float* Ab = OA + ((long)bh * Sd + qt * QT) * Sd;
    float* Cb = OC + ((long)bh * Sd + qt * QT) * Dd;

    if (t < 64) sinv[t] = g_inv[bh * Sd + qt * QT + t];

    auto stage = [&](int c, int buf) {
        const uint32_t pb = sb + B_SP + buf * 2 * TILE;
        const uint32_t vb = sb + B_SV + buf * 2 * TILE;
        const long vrow = (long)c * CH * Dd;
        #pragma unroll
        for (int half = 0; half < 2; ++half) {
            const int g = t + half * 256;
            const int r = g >> 3, u = g & 7;
            const uint32_t dofs = (uint32_t)((r * PIT + u * 8) * 2);
            const size_t po = (size_t)r * Sd + c * CH + u * 8;
            cpa16(pb + dofs, PHb + po);
            cpa16(pb + TILE + dofs, PLb + po);
            const long vo = vrow + r * Dd + u * 8;
            cpa16(vb + dofs, VHb + vo);
            cpa16(vb + TILE + dofs, VLb + vo);
        }
    };

    stage(0, 0);
    cpa_commit();

    float ctx[8][4];
    #pragma unroll
    for (int d = 0; d < 8; ++d)
        { ctx[d][0] = 0.f; ctx[d][1] = 0.f; ctx[d][2] = 0.f; ctx[d][3] = 0.f; }

    const int l2 = l & 15;
    const int voff = (l2 * PIT) * 2;
    cpa_wait0();
    __syncthreads();

    const float inv0 = sinv[16 * qw + gid];
    const float inv1 = sinv[16 * qw + gid + 8];
    float* arow0 = Ab + (long)(16 * qw + gid) * Sd;
    float* arow1 = arow0 + 8 * (long)Sd;

    for (int c = 0; c < NCH; ++c) {
        const int buf = c & 1;
        if (c + 1 < NCH) { stage(c + 1, buf ^ 1); cpa_commit(); }

        const uint32_t p_base = sb + B_SP + buf * 2 * TILE;
        const uint32_t vh_base = sb + B_SV + buf * 2 * TILE + voff;
        const uint32_t vl_base = vh_base + TILE;

        #pragma unroll
        for (int kt = 0; kt < 2; ++kt) {
            const int ktg = kh * 2 + kt;
            uint32_t ah[4], al[4];
            const int rowb =
                ((16 * qw + (l & 15)) * PIT + ktg * 16 + ((l >> 4) << 3)) * 2;
            ldm_x4(p_base + rowb, ah);
            ldm_x4(p_base + TILE + rowb, al);

            // Normalized attention straight from the fragments.
            {
                const int c0 = c * CH + ktg * 16 + 2 * qd;
                *(float2*)(arow0 + c0) = make_float2(
                    (lo16f(ah[0]) + lo16f(al[0])) * inv0,
                    (hi16f(ah[0]) + hi16f(al[0])) * inv0);
                *(float2*)(arow1 + c0) = make_float2(
                    (lo16f(ah[1]) + lo16f(al[1])) * inv1,
                    (hi16f(ah[1]) + hi16f(al[1])) * inv1);
                *(float2*)(arow0 + c0 + 8) = make_float2(
                    (lo16f(ah[2]) + lo16f(al[2])) * inv0,
                    (hi16f(ah[2]) + hi16f(al[2])) * inv0);
                *(float2*)(arow1 + c0 + 8) = make_float2(
                    (lo16f(ah[3]) + lo16f(al[3])) * inv1,
                    (hi16f(ah[3]) + hi16f(al[3])) * inv1);
            }

            const uint32_t vrow = (uint32_t)(ktg * 16 * PIT * 2);
            #pragma unroll
            for (int dt = 0; dt < 8; ++dt) {
                uint32_t vfh[2], vfl[2];
                ldm_x2t(vh_base + vrow + dt * 16, vfh);
                ldm_x2t(vl_base + vrow + dt * 16, vfl);
                mma_bf16(ctx[dt], ah, vfh);
                mma_bf16(ctx[dt], ah, vfl);
                mma_bf16(ctx[dt], al, vfh);
            }
        }
        if (c + 1 < NCH) cpa_wait0();
        __syncthreads();
    }

    const int r0 = 16 * qw + gid;
    float* cs = (float*)smem;             // 64 x 68 floats (P region dead)
    if (kh == 1) {
        #pragma unroll
        for (int dt = 0; dt < 8; ++dt) {
            *(float2*)(cs + r0 * 68 + dt * 8 + 2 * qd) =
                make_float2(ctx[dt][0], ctx[dt][1]);
            *(float2*)(cs + (r0 + 8) * 68 + dt * 8 + 2 * qd) =
                make_float2(ctx[dt][2], ctx[dt][3]);
        }
    }
    __syncthreads();
    if (kh == 0) {
        float* crow = Cb + (long)r0 * Dd + 2 * qd;
        #pragma unroll
        for (int dt = 0; dt < 8; ++dt) {
            const float2 p0 = *(const float2*)(cs + r0 * 68 + dt * 8 + 2 * qd);
            const float2 p1 = *(const float2*)(cs + (r0 + 8) * 68 + dt * 8 + 2 * qd);
            *(float2*)(crow + dt * 8) =
                make_float2((ctx[dt][0] + p0.x) * inv0, (ctx[dt][1] + p0.y) * inv0);
            *(float2*)(crow + dt * 8 + 8 * Dd) =
                make_float2((ctx[dt][2] + p1.x) * inv1, (ctx[dt][3] + p1.y) * inv1);
        }
    }
}

extern "C" void kernel_launch(void* const* d_in, const int* in_sizes, int n_in,
                              void* d_out, int out_size) {
    const float* Q = (const float*)d_in[0];
    const float* K = (const float*)d_in[1];
    const float* V = (const float*)d_in[2];
    const float* M = (const float*)d_in[3];

    float* ctx  = (float*)d_out;
    float* attn = (float*)d_out + (size_t)2 * 16 * 2048 * 64;

    cudaFuncSetAttribute(attn_qk_kernel,
                         cudaFuncAttributeMaxDynamicSharedMemorySize, A_SMEM);
    cudaFuncSetAttribute(attn_pv_kernel,
                         cudaFuncAttributeMaxDynamicSharedMemorySize, B_SMEM);

    conv_kv_kernel<<<4096, 256>>>(K, V);
    dim3 grid(Sd / QT, 32);   // (32, 32)
    attn_qk_kernel<<<grid, NT, A_SMEM>>>(Q, M);
    attn_pv_kernel<<<grid, NT, B_SMEM>>>(ctx, attn);
}

// round 13
// speedup vs baseline: 1.1379x; 1.1379x over previous
#include <cuda_runtime.h>
#include <cuda_bf16.h>
#include <cstdint>

namespace {
constexpr int Sd = 2048, Dd = 64, QT = 64, CH = 64, NCH = Sd / CH, NT = 256;
constexpr int PIT = 72;                      // bf16 row pitch (conflict-free LDSM)
constexpr int TILE = QT * PIT * 2;           // 9216 bytes per bf16 tile
// Q overlaid on K buf 1 (Q frags are register-resident before buf1 is staged).
constexpr int SK  = 0;                       // K: 2 bufs x (hi+lo)
constexpr int SQH = SK + 2 * TILE, SQL = SK + 3 * TILE;
constexpr int SV  = 4 * TILE;                // V: 2 bufs x (hi+lo)
constexpr int SMEM_BYTES = 8 * TILE + 256;   // 73984

__device__ float g_inv[65536];
__device__ __nv_bfloat16 g_KH[2 * 16 * 2048 * 64];
__device__ __nv_bfloat16 g_KL[2 * 16 * 2048 * 64];
__device__ __nv_bfloat16 g_VH[2 * 16 * 2048 * 64];
__device__ __nv_bfloat16 g_VL[2 * 16 * 2048 * 64];

__device__ __forceinline__ uint32_t smem_u32(const void* p) {
    uint32_t a;
    asm("{ .reg .u64 t; cvta.to.shared.u64 t, %1; cvt.u32.u64 %0, t; }"
        : "=r"(a) : "l"(p));
    return a;
}
__device__ __forceinline__ uint32_t pack2(float a, float b) {  // lo=a, hi=b
    uint32_t r;
    asm("cvt.rn.bf16x2.f32 %0, %1, %2;" : "=r"(r) : "f"(b), "f"(a));
    return r;
}
__device__ __forceinline__ float bfr(float x) {
    return __bfloat162float(__float2bfloat16(x));
}
__device__ __forceinline__ void ldm_x4(uint32_t a, uint32_t* r) {
    asm volatile("ldmatrix.sync.aligned.m8n8.x4.shared.b16 {%0,%1,%2,%3}, [%4];"
                 : "=r"(r[0]), "=r"(r[1]), "=r"(r[2]), "=r"(r[3]) : "r"(a));
}
__device__ __forceinline__ void ldm_x2(uint32_t a, uint32_t* r) {
    asm volatile("ldmatrix.sync.aligned.m8n8.x2.shared.b16 {%0,%1}, [%2];"
                 : "=r"(r[0]), "=r"(r[1]) : "r"(a));
}
__device__ __forceinline__ void ldm_x2t(uint32_t a, uint32_t* r) {
    asm volatile("ldmatrix.sync.aligned.m8n8.x2.trans.shared.b16 {%0,%1}, [%2];"
                 : "=r"(r[0]), "=r"(r[1]) : "r"(a));
}
__device__ __forceinline__ void mma_bf16(float* d, const uint32_t* a,
                                         const uint32_t* b) {
    asm volatile(
        "mma.sync.aligned.m16n8k16.row.col.f32.bf16.bf16.f32 "
        "{%0,%1,%2,%3}, {%4,%5,%6,%7}, {%8,%9}, {%0,%1,%2,%3};"
        : "+f"(d[0]), "+f"(d[1]), "+f"(d[2]), "+f"(d[3])
        : "r"(a[0]), "r"(a[1]), "r"(a[2]), "r"(a[3]), "r"(b[0]), "r"(b[1]));
}
__device__ __forceinline__ void cpa16(uint32_t dst, const void* src) {
    asm volatile("cp.async.cg.shared.global [%0], [%1], 16;"
                 :: "r"(dst), "l"(src));
}
__device__ __forceinline__ void cpa_commit() {
    asm volatile("cp.async.commit_group;" ::: "memory");
}
__device__ __forceinline__ void cpa_wait0() {
    asm volatile("cp.async.wait_group 0;" ::: "memory");
}
constexpr float L2E = 1.4426950408889634f;
} // namespace

// ---------------- prepass: fp32 K/V -> bf16 hi/lo scratch -------------------
__global__ void __launch_bounds__(256, 8)
conv_kv_kernel(const float* __restrict__ K, const float* __restrict__ V)
{
    const size_t i4 = (size_t)blockIdx.x * 256 + threadIdx.x;
    const float4 kv = *(const float4*)(K + i4 * 4);
    const float4 vv = *(const float4*)(V + i4 * 4);
    const float khx = bfr(kv.x), khy = bfr(kv.y), khz = bfr(kv.z), khw = bfr(kv.w);
    const float vhx = bfr(vv.x), vhy = bfr(vv.y), vhz = bfr(vv.z), vhw = bfr(vv.w);
    ((uint2*)g_KH)[i4] = make_uint2(pack2(kv.x, kv.y), pack2(kv.z, kv.w));
    ((uint2*)g_KL)[i4] =
        make_uint2(pack2(kv.x - khx, kv.y - khy), pack2(kv.z - khz, kv.w - khw));
    ((uint2*)g_VH)[i4] = make_uint2(pack2(vv.x, vv.y), pack2(vv.z, vv.w));
    ((uint2*)g_VL)[i4] =
        make_uint2(pack2(vv.x - vhx, vv.y - vhy), pack2(vv.z - vhz, vv.w - vhw));
}

// ---------------------------- main kernel -----------------------------------
__global__ void __launch_bounds__(NT, 2)
attn_mma_kernel(const float* __restrict__ Q, const float* __restrict__ Mk,
                float* __restrict__ OC, float* __restrict__ OA)
{
    extern __shared__ char smem[];
    const uint32_t sb = smem_u32(smem);

    const int t = threadIdx.x, w = t >> 5, l = t & 31;
    const int qw = w & 3, kh = w >> 2;
    const int gid = l >> 2, qd = l & 3;
    const int qt = blockIdx.x, bh = blockIdx.y;

    const float* Qb = Q + ((long)bh * Sd + qt * QT) * Dd;
    const float* Mb = Mk + ((long)bh * Sd + qt * QT) * Sd;
    float*       Ab = OA + ((long)bh * Sd + qt * QT) * Sd;
    float*       Cb = OC + ((long)bh * Sd + qt * QT) * Dd;

    const __nv_bfloat16* KHb = g_KH + (long)bh * Sd * Dd;
    const __nv_bfloat16* KLb = g_KL + (long)bh * Sd * Dd;
    const __nv_bfloat16* VHb = g_VH + (long)bh * Sd * Dd;
    const __nv_bfloat16* VLb = g_VL + (long)bh * Sd * Dd;

    auto stage = [&](int c, int buf) {
        const long srow = (long)c * CH * Dd;
        const uint32_t kb = sb + SK + buf * 2 * TILE;
        const uint32_t vb = sb + SV + buf * 2 * TILE;
        #pragma unroll
        for (int half = 0; half < 2; ++half) {
            const int g = t + half * 256;
            const int r = g >> 3, u = g & 7;
            const long so = srow + r * Dd + u * 8;
            const uint32_t dofs = (uint32_t)((r * PIT + u * 8) * 2);
            cpa16(kb + dofs, KHb + so);
            cpa16(kb + TILE + dofs, KLb + so);
            cpa16(vb + dofs, VHb + so);
            cpa16(vb + TILE + dofs, VLb + so);
        }
    };

    stage(0, 0);
    cpa_commit();
    // Q convert (x 1/8 x log2(e)), into the (currently free) K buf-1 region.
    #pragma unroll
    for (int i = 0; i < 4; ++i) {
        const int idx4 = t + NT * i;
        const int row = idx4 >> 4, c4 = (idx4 & 15) << 2;
        float4 v = *(const float4*)(Qb + (size_t)idx4 * 4);
        const float qs = 0.125f * L2E;
        v.x *= qs; v.y *= qs; v.z *= qs; v.w *= qs;
        const float hx = bfr(v.x), hy = bfr(v.y), hz = bfr(v.z), hw = bfr(v.w);
        const int boff = (row * PIT + c4) * 2;
        *(uint2*)(smem + SQH + boff) = make_uint2(pack2(v.x, v.y), pack2(v.z, v.w));
        *(uint2*)(smem + SQL + boff) =
            make_uint2(pack2(v.x - hx, v.y - hy), pack2(v.z - hz, v.w - hw));
    }
    __syncthreads();

    uint32_t qh[4][4], ql[4][4];
    {
        const int rowb = ((16 * qw + (l & 15)) * PIT + ((l >> 4) << 3)) * 2;
        #pragma unroll
        for (int kt = 0; kt < 4; ++kt) {
            ldm_x4(sb + SQH + rowb + kt * 32, qh[kt]);
            ldm_x4(sb + SQL + rowb + kt * 32, ql[kt]);
        }
    }
    cpa_wait0();
    __syncthreads();   // Q frags in regs; buf-1 region may now be overwritten

    float ctx[8][4];
    #pragma unroll
    for (int d = 0; d < 8; ++d)
        { ctx[d][0] = 0.f; ctx[d][1] = 0.f; ctx[d][2] = 0.f; ctx[d][3] = 0.f; }
    float rs0 = 0.f, rs1 = 0.f;

    const int l2 = l & 15;
    const int koff = ((l2 & 7) * PIT + ((l2 >> 3) << 3)) * 2;
    const int voff = (l2 * PIT) * 2;

    const float* mrow = Mb + (long)(16 * qw + gid) * Sd + kh * 32 + 2 * qd;
    float*       arow = Ab + (long)(16 * qw + gid) * Sd + kh * 32 + 2 * qd;

    // Mask pipeline: chunk-0 mask loaded up front.
    float2 mk0[4], mk1[4];
    #pragma unroll
    for (int nt = 0; nt < 4; ++nt) {
        mk0[nt] = *(const float2*)(mrow + nt * 8);
        mk1[nt] = *(const float2*)(mrow + nt * 8 + 8 * (long)Sd);
    }

    for (int c = 0; c < NCH; ++c) {
        const int buf = c & 1;
        if (c + 1 < NCH) { stage(c + 1, buf ^ 1); cpa_commit(); }

        const int cb = c * CH;
        const uint32_t kh_base = sb + SK + buf * 2 * TILE + koff;
        const uint32_t kl_base = kh_base + TILE;
        const uint32_t vh_base = sb + SV + buf * 2 * TILE + voff;
        const uint32_t vl_base = vh_base + TILE;

        uint32_t Ph[8], Pl[8];
        #pragma unroll
        for (int nt = 0; nt < 4; ++nt) {
            const int ntg = kh * 4 + nt;
            float sA[4] = {0.f,0.f,0.f,0.f};
            float sB[4] = {0.f,0.f,0.f,0.f};
            float sC[4] = {0.f,0.f,0.f,0.f};
            #pragma unroll
            for (int kt = 0; kt < 4; ++kt) {
                const uint32_t off = (uint32_t)(ntg * 8 * PIT * 2 + kt * 32);
                uint32_t kfh[2], kfl[2];
                ldm_x2(kh_base + off, kfh);
                ldm_x2(kl_base + off, kfl);
                mma_bf16(sA, qh[kt], kfh);
                mma_bf16(sB, qh[kt], kfl);
                mma_bf16(sC, ql[kt], kfh);
            }
            // e = 2^(s + m*log2e); Q already carries the log2e factor.
            const float e0 = exp2f(fmaf(mk0[nt].x, L2E, (sA[0] + sB[0]) + sC[0]));
            const float e1 = exp2f(fmaf(mk0[nt].y, L2E, (sA[1] + sB[1]) + sC[1]));
            const float e2 = exp2f(fmaf(mk1[nt].x, L2E, (sA[2] + sB[2]) + sC[2]));
            const float e3 = exp2f(fmaf(mk1[nt].y, L2E, (sA[3] + sB[3]) + sC[3]));
            rs0 += e0 + e1; rs1 += e2 + e3;
            *(float2*)(arow + cb + nt * 8) = make_float2(e0, e1);
            *(float2*)(arow + cb + nt * 8 + 8 * (long)Sd) = make_float2(e2, e3);
            const float h0 = bfr(e0), h1 = bfr(e1), h2 = bfr(e2), h3 = bfr(e3);
            Ph[2 * nt]     = pack2(e0, e1);
            Ph[2 * nt + 1] = pack2(e2, e3);
            Pl[2 * nt]     = pack2(e0 - h0, e1 - h1);
            Pl[2 * nt + 1] = pack2(e2 - h2, e3 - h3);
        }

        // Prefetch next chunk's mask now (mk dead; ~PV-phase + sync ahead of use).
        if (c + 1 < NCH) {
            const int cn = (c + 1) * CH;
            #pragma unroll
            for (int nt = 0; nt < 4; ++nt) {
                mk0[nt] = *(const float2*)(mrow + cn + nt * 8);
                mk1[nt] = *(const float2*)(mrow + cn + nt * 8 + 8 * (long)Sd);
            }
        }

        #pragma unroll
        for (int kt = 0; kt < 2; ++kt) {
            const int ktg = kh * 2 + kt;
            const uint32_t* ah = Ph + 4 * kt;
            const uint32_t* al = Pl + 4 * kt;
            const uint32_t vrow = (uint32_t)(ktg * 16 * PIT * 2);
            #pragma unroll
            for (int dt = 0; dt < 8; ++dt) {
                uint32_t vfh[2], vfl[2];
                ldm_x2t(vh_base + vrow + dt * 16, vfh);
                ldm_x2t(vl_base + vrow + dt * 16, vfl);
                mma_bf16(ctx[dt], ah, vfh);
                mma_bf16(ctx[dt], ah, vfl);
                mma_bf16(ctx[dt], al, vfh);
            }
        }
        if (c + 1 < NCH) cpa_wait0();
        __syncthreads();
    }

    // rowsum: quad-reduce, then combine the two k-halves through smem.
    #pragma unroll
    for (int o = 1; o < 4; o <<= 1) {
        rs0 += __shfl_xor_sync(0xffffffffu, rs0, o);
        rs1 += __shfl_xor_sync(0xffffffffu, rs1, o);
    }
    float* srs = (float*)smem;            // [2][64]
    if (qd == 0) {
        srs[kh * 64 + 16 * qw + gid]     = rs0;
        srs[kh * 64 + 16 * qw + gid + 8] = rs1;
    }
    __syncthreads();
    const int r0 = 16 * qw + gid;
    const float inv0 = 1.0f / (srs[r0] + srs[64 + r0]);
    const float inv1 = 1.0f / (srs[r0 + 8] + srs[64 + r0 + 8]);
    if (qd == 0 && kh == 0) {
        const int grow = bh * Sd + qt * QT + r0;
        g_inv[grow]     = inv0;
        g_inv[grow + 8] = inv1;
    }

    // ctx: half 1 publishes partials (pitch-68), half 0 adds + stores.
    float* cs = (float*)(smem + 1024);    // 64 x 68 floats
    if (kh == 1) {
        #pragma unroll
        for (int dt = 0; dt < 8; ++dt) {
            *(float2*)(cs + r0 * 68 + dt * 8 + 2 * qd) =
                make_float2(ctx[dt][0], ctx[dt][1]);
            *(float2*)(cs + (r0 + 8) * 68 + dt * 8 + 2 * qd) =
                make_float2(ctx[dt][2], ctx[dt][3]);
        }
    }
    __syncthreads();
    if (kh == 0) {
        float* crow = Cb + (long)r0 * Dd + 2 * qd;
        #pragma unroll
        for (int dt = 0; dt < 8; ++dt) {
            const float2 p0 = *(const float2*)(cs + r0 * 68 + dt * 8 + 2 * qd);
            const float2 p1 = *(const float2*)(cs + (r0 + 8) * 68 + dt * 8 + 2 * qd);
            *(float2*)(crow + dt * 8) =
                make_float2((ctx[dt][0] + p0.x) * inv0, (ctx[dt][1] + p0.y) * inv0);
            *(float2*)(crow + dt * 8 + 8 * Dd) =
                make_float2((ctx[dt][2] + p1.x) * inv1, (ctx[dt][3] + p1.y) * inv1);
        }
    }
}

__global__ void __launch_bounds__(256, 8)
attn_norm_kernel(float* __restrict__ A)
{
    const size_t i = ((size_t)blockIdx.x * 256 + threadIdx.x) * 4;
    const int row = (int)(i >> 11);
    float4 v = *(float4*)(A + i);
    const float s = g_inv[row];
    v.x *= s; v.y *= s; v.z *= s; v.w *= s;
    *(float4*)(A + i) = v;
}

extern "C" void kernel_launch(void* const* d_in, const int* in_sizes, int n_in,
                              void* d_out, int out_size) {
    const float* Q = (const float*)d_in[0];
    const float* K = (const float*)d_in[1];
    const float* V = (const float*)d_in[2];
    const float* M = (const float*)d_in[3];

    float* ctx  = (float*)d_out;
    float* attn = (float*)d_out + (size_t)2 * 16 * 2048 * 64;

    cudaFuncSetAttribute(attn_mma_kernel,
                         cudaFuncAttributeMaxDynamicSharedMemorySize, SMEM_BYTES);

    conv_kv_kernel<<<4096, 256>>>(K, V);

    dim3 grid(Sd / QT, 32);   // (32, 32)
    attn_mma_kernel<<<grid, NT, SMEM_BYTES>>>(Q, M, ctx, attn);

    const size_t total4 = (size_t)32 * 2048 * 2048 / 4;
    attn_norm_kernel<<<(unsigned)(total4 / 256), 256>>>(attn);
}

// round 15
// speedup vs baseline: 1.1849x; 1.0413x over previous
#include <cuda_runtime.h>
#include <cuda_bf16.h>
#include <cuda_fp16.h>
#include <cstdint>

namespace {
constexpr int Sd = 2048, Dd = 64, QT = 64, CH = 64, NCH = Sd / CH, NT = 256;
constexpr int PIT = 72;                      // bf16 row pitch (conflict-free LDSM)
constexpr int TILE = QT * PIT * 2;           // 9216 bytes per bf16 tile
// Q overlaid on K buf 1 (Q frags are register-resident before buf1 is staged).
constexpr int SK  = 0;                       // K: 2 bufs x (hi+lo)
constexpr int SQH = SK + 2 * TILE, SQL = SK + 3 * TILE;
constexpr int SV  = 4 * TILE;                // V: 2 bufs x (hi+lo)
constexpr int SMEM_BYTES = 8 * TILE + 256;   // 73984

__device__ float g_inv[65536];
__device__ __nv_bfloat16 g_KH[2 * 16 * 2048 * 64];
__device__ __nv_bfloat16 g_KL[2 * 16 * 2048 * 64];
__device__ __nv_bfloat16 g_VH[2 * 16 * 2048 * 64];
__device__ __nv_bfloat16 g_VL[2 * 16 * 2048 * 64];
// fp16 unnormalized attention intermediate (268 MB).
__device__ __half g_Pf[(size_t)32 * 2048 * 2048];

__device__ __forceinline__ uint32_t smem_u32(const void* p) {
    uint32_t a;
    asm("{ .reg .u64 t; cvta.to.shared.u64 t, %1; cvt.u32.u64 %0, t; }"
        : "=r"(a) : "l"(p));
    return a;
}
__device__ __forceinline__ uint32_t pack2(float a, float b) {  // lo=a, hi=b
    uint32_t r;
    asm("cvt.rn.bf16x2.f32 %0, %1, %2;" : "=r"(r) : "f"(b), "f"(a));
    return r;
}
__device__ __forceinline__ uint32_t packh2(float a, float b) { // fp16 pair
    uint32_t r;
    asm("cvt.rn.f16x2.f32 %0, %1, %2;" : "=r"(r) : "f"(b), "f"(a));
    return r;
}
__device__ __forceinline__ float bfr(float x) {
    return __bfloat162float(__float2bfloat16(x));
}
__device__ __forceinline__ void ldm_x4(uint32_t a, uint32_t* r) {
    asm volatile("ldmatrix.sync.aligned.m8n8.x4.shared.b16 {%0,%1,%2,%3}, [%4];"
                 : "=r"(r[0]), "=r"(r[1]), "=r"(r[2]), "=r"(r[3]) : "r"(a));
}
__device__ __forceinline__ void ldm_x2(uint32_t a, uint32_t* r) {
    asm volatile("ldmatrix.sync.aligned.m8n8.x2.shared.b16 {%0,%1}, [%2];"
                 : "=r"(r[0]), "=r"(r[1]) : "r"(a));
}
__device__ __forceinline__ void ldm_x2t(uint32_t a, uint32_t* r) {
    asm volatile("ldmatrix.sync.aligned.m8n8.x2.trans.shared.b16 {%0,%1}, [%2];"
                 : "=r"(r[0]), "=r"(r[1]) : "r"(a));
}
__device__ __forceinline__ void mma_bf16(float* d, const uint32_t* a,
                                         const uint32_t* b) {
    asm volatile(
        "mma.sync.aligned.m16n8k16.row.col.f32.bf16.bf16.f32 "
        "{%0,%1,%2,%3}, {%4,%5,%6,%7}, {%8,%9}, {%0,%1,%2,%3};"
        : "+f"(d[0]), "+f"(d[1]), "+f"(d[2]), "+f"(d[3])
        : "r"(a[0]), "r"(a[1]), "r"(a[2]), "r"(a[3]), "r"(b[0]), "r"(b[1]));
}
__device__ __forceinline__ void cpa16(uint32_t dst, const void* src) {
    asm volatile("cp.async.cg.shared.global [%0], [%1], 16;"
                 :: "r"(dst), "l"(src));
}
__device__ __forceinline__ void cpa_commit() {
    asm volatile("cp.async.commit_group;" ::: "memory");
}
__device__ __forceinline__ void cpa_wait0() {
    asm volatile("cp.async.wait_group 0;" ::: "memory");
}
constexpr float L2E = 1.4426950408889634f;
} // namespace

// ---------------- prepass: fp32 K/V -> bf16 hi/lo scratch -------------------
__global__ void __launch_bounds__(256, 8)
conv_kv_kernel(const float* __restrict__ K, const float* __restrict__ V)
{
    const size_t i4 = (size_t)blockIdx.x * 256 + threadIdx.x;
    const float4 kv = *(const float4*)(K + i4 * 4);
    const float4 vv = *(const float4*)(V + i4 * 4);
    const float khx = bfr(kv.x), khy = bfr(kv.y), khz = bfr(kv.z), khw = bfr(kv.w);
    const float vhx = bfr(vv.x), vhy = bfr(vv.y), vhz = bfr(vv.z), vhw = bfr(vv.w);
    ((uint2*)g_KH)[i4] = make_uint2(pack2(kv.x, kv.y), pack2(kv.z, kv.w));
    ((uint2*)g_KL)[i4] =
        make_uint2(pack2(kv.x - khx, kv.y - khy), pack2(kv.z - khz, kv.w - khw));
    ((uint2*)g_VH)[i4] = make_uint2(pack2(vv.x, vv.y), pack2(vv.z, vv.w));
    ((uint2*)g_VL)[i4] =
        make_uint2(pack2(vv.x - vhx, vv.y - vhy), pack2(vv.z - vhz, vv.w - vhw));
}

// ---------------------------- main kernel -----------------------------------
__global__ void __launch_bounds__(NT, 2)
attn_mma_kernel(const float* __restrict__ Q, const float* __restrict__ Mk,
                float* __restrict__ OC)
{
    extern __shared__ char smem[];
    const uint32_t sb = smem_u32(smem);

    const int t = threadIdx.x, w = t >> 5, l = t & 31;
    const int qw = w & 3, kh = w >> 2;
    const int gid = l >> 2, qd = l & 3;
    const int qt = blockIdx.x, bh = blockIdx.y;

    const float* Qb = Q + ((long)bh * Sd + qt * QT) * Dd;
    const float* Mb = Mk + ((long)bh * Sd + qt * QT) * Sd;
    float*       Cb = OC + ((long)bh * Sd + qt * QT) * Dd;

    const __nv_bfloat16* KHb = g_KH + (long)bh * Sd * Dd;
    const __nv_bfloat16* KLb = g_KL + (long)bh * Sd * Dd;
    const __nv_bfloat16* VHb = g_VH + (long)bh * Sd * Dd;
    const __nv_bfloat16* VLb = g_VL + (long)bh * Sd * Dd;

    auto stage = [&](int c, int buf) {
        const long srow = (long)c * CH * Dd;
        const uint32_t kb = sb + SK + buf * 2 * TILE;
        const uint32_t vb = sb + SV + buf * 2 * TILE;
        #pragma unroll
        for (int half = 0; half < 2; ++half) {
            const int g = t + half * 256;
            const int r = g >> 3, u = g & 7;
            const long so = srow + r * Dd + u * 8;
            const uint32_t dofs = (uint32_t)((r * PIT + u * 8) * 2);
            cpa16(kb + dofs, KHb + so);
            cpa16(kb + TILE + dofs, KLb + so);
            cpa16(vb + dofs, VHb + so);
            cpa16(vb + TILE + dofs, VLb + so);
        }
    };

    stage(0, 0);
    cpa_commit();
    // Q convert (x 1/8 x log2(e)), into the (currently free) K buf-1 region.
    #pragma unroll
    for (int i = 0; i < 4; ++i) {
        const int idx4 = t + NT * i;
        const int row = idx4 >> 4, c4 = (idx4 & 15) << 2;
        float4 v = *(const float4*)(Qb + (size_t)idx4 * 4);
        const float qs = 0.125f * L2E;
        v.x *= qs; v.y *= qs; v.z *= qs; v.w *= qs;
        const float hx = bfr(v.x), hy = bfr(v.y), hz = bfr(v.z), hw = bfr(v.w);
        const int boff = (row * PIT + c4) * 2;
        *(uint2*)(smem + SQH + boff) = make_uint2(pack2(v.x, v.y), pack2(v.z, v.w));
        *(uint2*)(smem + SQL + boff) =
            make_uint2(pack2(v.x - hx, v.y - hy), pack2(v.z - hz, v.w - hw));
    }
    __syncthreads();

    uint32_t qh[4][4], ql[4][4];
    {
        const int rowb = ((16 * qw + (l & 15)) * PIT + ((l >> 4) << 3)) * 2;
        #pragma unroll
        for (int kt = 0; kt < 4; ++kt) {
            ldm_x4(sb + SQH + rowb + kt * 32, qh[kt]);
            ldm_x4(sb + SQL + rowb + kt * 32, ql[kt]);
        }
    }
    cpa_wait0();
    __syncthreads();   // Q frags in regs; buf-1 region may now be overwritten

    float ctx[8][4];
    #pragma unroll
    for (int d = 0; d < 8; ++d)
        { ctx[d][0] = 0.f; ctx[d][1] = 0.f; ctx[d][2] = 0.f; ctx[d][3] = 0.f; }
    float rs0 = 0.f, rs1 = 0.f;

    const int l2 = l & 15;
    const int koff = ((l2 & 7) * PIT + ((l2 >> 3) << 3)) * 2;
    const int voff = (l2 * PIT) * 2;

    const float* mrow = Mb + (long)(16 * qw + gid) * Sd + kh * 32 + 2 * qd;

    // fp16 attention plane, u32 granules (2 cols each).
    uint32_t* PfU = (uint32_t*)g_Pf;
    const size_t prow0 =
        ((size_t)bh * Sd + qt * QT + 16 * qw + gid) * (Sd / 2) + kh * 16 + qd;
    const size_t prow8 = prow0 + 8 * (size_t)(Sd / 2);

    // Mask pipeline: chunk-0 mask loaded up front.
    float2 mk0[4], mk1[4];
    #pragma unroll
    for (int nt = 0; nt < 4; ++nt) {
        mk0[nt] = *(const float2*)(mrow + nt * 8);
        mk1[nt] = *(const float2*)(mrow + nt * 8 + 8 * (long)Sd);
    }

    for (int c = 0; c < NCH; ++c) {
        const int buf = c & 1;
        if (c + 1 < NCH) { stage(c + 1, buf ^ 1); cpa_commit(); }

        const uint32_t kh_base = sb + SK + buf * 2 * TILE + koff;
        const uint32_t kl_base = kh_base + TILE;
        const uint32_t vh_base = sb + SV + buf * 2 * TILE + voff;
        const uint32_t vl_base = vh_base + TILE;

        uint32_t Ph[8], Pl[8];
        #pragma unroll
        for (int nt = 0; nt < 4; ++nt) {
            const int ntg = kh * 4 + nt;
            float sA[4] = {0.f,0.f,0.f,0.f};
            float sB[4] = {0.f,0.f,0.f,0.f};
            float sC[4] = {0.f,0.f,0.f,0.f};
            #pragma unroll
            for (int kt = 0; kt < 4; ++kt) {
                const uint32_t off = (uint32_t)(ntg * 8 * PIT * 2 + kt * 32);
                uint32_t kfh[2], kfl[2];
                ldm_x2(kh_base + off, kfh);
                ldm_x2(kl_base + off, kfl);
                mma_bf16(sA, qh[kt], kfh);
                mma_bf16(sB, qh[kt], kfl);
                mma_bf16(sC, ql[kt], kfh);
            }
            // e = 2^(s + m*log2e); Q already carries the log2e factor.
            const float e0 = exp2f(fmaf(mk0[nt].x, L2E, (sA[0] + sB[0]) + sC[0]));
            const float e1 = exp2f(fmaf(mk0[nt].y, L2E, (sA[1] + sB[1]) + sC[1]));
            const float e2 = exp2f(fmaf(mk1[nt].x, L2E, (sA[2] + sB[2]) + sC[2]));
            const float e3 = exp2f(fmaf(mk1[nt].y, L2E, (sA[3] + sB[3]) + sC[3]));
            rs0 += e0 + e1; rs1 += e2 + e3;
            const float h0 = bfr(e0), h1 = bfr(e1), h2 = bfr(e2), h3 = bfr(e3);
            Ph[2 * nt]     = pack2(e0, e1);
            Ph[2 * nt + 1] = pack2(e2, e3);
            Pl[2 * nt]     = pack2(e0 - h0, e1 - h1);
            Pl[2 * nt + 1] = pack2(e2 - h2, e3 - h3);
            // fp16 attention store: one u32 per (row, 2-col) pair.
            const size_t ci = (size_t)c * 32 + nt * 4;
            PfU[prow0 + ci] = packh2(e0, e1);
            PfU[prow8 + ci] = packh2(e2, e3);
        }

        // Prefetch next chunk's mask (mk regs dead; lands ~PV-phase ahead of use).
        if (c + 1 < NCH) {
            const int cn = (c + 1) * CH;
            #pragma unroll
            for (int nt = 0; nt < 4; ++nt) {
                mk0[nt] = *(const float2*)(mrow + cn + nt * 8);
                mk1[nt] = *(const float2*)(mrow + cn + nt * 8 + 8 * (long)Sd);
            }
        }

        #pragma unroll
        for (int kt = 0; kt < 2; ++kt) {
            const int ktg = kh * 2 + kt;
            const uint32_t* ah = Ph + 4 * kt;
            const uint32_t* al = Pl + 4 * kt;
            const uint32_t vrow = (uint32_t)(ktg * 16 * PIT * 2);
            #pragma unroll
            for (int dt = 0; dt < 8; ++dt) {
                uint32_t vfh[2], vfl[2];
                ldm_x2t(vh_base + vrow + dt * 16, vfh);
                ldm_x2t(vl_base + vrow + dt * 16, vfl);
                mma_bf16(ctx[dt], ah, vfh);
                mma_bf16(ctx[dt], ah, vfl);
                mma_bf16(ctx[dt], al, vfh);
            }
        }
        if (c + 1 < NCH) cpa_wait0();
        __syncthreads();
    }

    // rowsum: quad-reduce, then combine the two k-halves through smem.
    #pragma unroll
    for (int o = 1; o < 4; o <<= 1) {
        rs0 += __shfl_xor_sync(0xffffffffu, rs0, o);
        rs1 += __shfl_xor_sync(0xffffffffu, rs1, o);
    }
    float* srs = (float*)smem;            // [2][64]
    if (qd == 0) {
        srs[kh * 64 + 16 * qw + gid]     = rs0;
        srs[kh * 64 + 16 * qw + gid + 8] = rs1;
    }
    __syncthreads();
    const int r0 = 16 * qw + gid;
    const float inv0 = 1.0f / (srs[r0] + srs[64 + r0]);
    const float inv1 = 1.0f / (srs[r0 + 8] + srs[64 + r0 + 8]);
    if (qd == 0 && kh == 0) {
        const int grow = bh * Sd + qt * QT + r0;
        g_inv[grow]     = inv0;
        g_inv[grow + 8] = inv1;
    }

    // ctx: half 1 publishes partials (pitch-68), half 0 adds + stores.
    float* cs = (float*)(smem + 1024);    // 64 x 68 floats
    if (kh == 1) {
        #pragma unroll
        for (int dt = 0; dt < 8; ++dt) {
            *(float2*)(cs + r0 * 68 + dt * 8 + 2 * qd) =
                make_float2(ctx[dt][0], ctx[dt][1]);
            *(float2*)(cs + (r0 + 8) * 68 + dt * 8 + 2 * qd) =
                make_float2(ctx[dt][2], ctx[dt][3]);
        }
    }
    __syncthreads();
    if (kh == 0) {
        float* crow = Cb + (long)r0 * Dd + 2 * qd;
        #pragma unroll
        for (int dt = 0; dt < 8; ++dt) {
            const float2 p0 = *(const float2*)(cs + r0 * 68 + dt * 8 + 2 * qd);
            const float2 p1 = *(const float2*)(cs + (r0 + 8) * 68 + dt * 8 + 2 * qd);
            *(float2*)(crow + dt * 8) =
                make_float2((ctx[dt][0] + p0.x) * inv0, (ctx[dt][1] + p0.y) * inv0);
            *(float2*)(crow + dt * 8 + 8 * Dd) =
                make_float2((ctx[dt][2] + p1.x) * inv1, (ctx[dt][3] + p1.y) * inv1);
        }
    }
}

// ---------- norm: fp16 unnormalized attn -> fp32 normalized attn ------------
__global__ void __launch_bounds__(256, 8)
attn_norm_kernel(float* __restrict__ A)
{
    const size_t i = (size_t)blockIdx.x * 256 + threadIdx.x;  // uint4 = 8 cols
    const uint4 u = ((const uint4*)g_Pf)[i];
    const size_t col0 = i * 8;
    const float s = g_inv[col0 >> 11];
    const float2 f0 = __half22float2(*(const __half2*)&u.x);
    const float2 f1 = __half22float2(*(const __half2*)&u.y);
    const float2 f2 = __half22float2(*(const __half2*)&u.z);
    const float2 f3 = __half22float2(*(const __half2*)&u.w);
    float4 o0, o1;
    o0.x = f0.x * s; o0.y = f0.y * s; o0.z = f1.x * s; o0.w = f1.y * s;
    o1.x = f2.x * s; o1.y = f2.y * s; o1.z = f3.x * s; o1.w = f3.y * s;
    *(float4*)(A + col0) = o0;
    *(float4*)(A + col0 + 4) = o1;
}

extern "C" void kernel_launch(void* const* d_in, const int* in_sizes, int n_in,
                              void* d_out, int out_size) {
    const float* Q = (const float*)d_in[0];
    const float* K = (const float*)d_in[1];
    const float* V = (const float*)d_in[2];
    const float* M = (const float*)d_in[3];

    float* ctx  = (float*)d_out;
    float* attn = (float*)d_out + (size_t)2 * 16 * 2048 * 64;

    cudaFuncSetAttribute(attn_mma_kernel,
                         cudaFuncAttributeMaxDynamicSharedMemorySize, SMEM_BYTES);

    conv_kv_kernel<<<4096, 256>>>(K, V);

    dim3 grid(Sd / QT, 32);   // (32, 32)
    attn_mma_kernel<<<grid, NT, SMEM_BYTES>>>(Q, M, ctx);

    const size_t total8 = (size_t)32 * 2048 * 2048 / 8;   // 8 cols per thread
    attn_norm_kernel<<<(unsigned)(total8 / 256), 256>>>(attn);
}

// round 16
// speedup vs baseline: 1.2215x; 1.0308x over previous
#include <cuda_runtime.h>
#include <cuda_bf16.h>
#include <cuda_fp16.h>
#include <cstdint>

namespace {
constexpr int Sd = 2048, Dd = 64, QT = 64, CH = 64, NCH = Sd / CH, NT = 256;
constexpr int PIT = 72;                      // 16-bit row pitch (conflict-free LDSM)
constexpr int TILE = QT * PIT * 2;           // 9216 bytes per tile
// Q overlaid on K buf 1 (Q frags are register-resident before buf1 is staged).
constexpr int SK  = 0;                       // K: 2 bufs x (hi+lo)
constexpr int SQH = SK + 2 * TILE, SQL = SK + 3 * TILE;
constexpr int SV  = 4 * TILE;                // V: 2 bufs x (hi+lo)
constexpr int SMEM_BYTES = 8 * TILE + 256;   // 73984

__device__ float g_inv[65536];
__device__ __nv_bfloat16 g_KH[2 * 16 * 2048 * 64];
__device__ __nv_bfloat16 g_KL[2 * 16 * 2048 * 64];
__device__ __half        g_VH[2 * 16 * 2048 * 64];   // fp16 V hi
__device__ __half        g_VL[2 * 16 * 2048 * 64];   // fp16 V residual
// fp16 unnormalized attention intermediate (268 MB).
__device__ __half g_Pf[(size_t)32 * 2048 * 2048];

__device__ __forceinline__ uint32_t smem_u32(const void* p) {
    uint32_t a;
    asm("{ .reg .u64 t; cvta.to.shared.u64 t, %1; cvt.u32.u64 %0, t; }"
        : "=r"(a) : "l"(p));
    return a;
}
__device__ __forceinline__ uint32_t pack2(float a, float b) {  // bf16: lo=a, hi=b
    uint32_t r;
    asm("cvt.rn.bf16x2.f32 %0, %1, %2;" : "=r"(r) : "f"(b), "f"(a));
    return r;
}
__device__ __forceinline__ uint32_t packh2(float a, float b) { // fp16: lo=a, hi=b
    uint32_t r;
    asm("cvt.rn.f16x2.f32 %0, %1, %2;" : "=r"(r) : "f"(b), "f"(a));
    return r;
}
__device__ __forceinline__ float bfr(float x) {
    return __bfloat162float(__float2bfloat16(x));
}
__device__ __forceinline__ float hfr(float x) {
    return __half2float(__float2half_rn(x));
}
__device__ __forceinline__ void ldm_x4(uint32_t a, uint32_t* r) {
    asm volatile("ldmatrix.sync.aligned.m8n8.x4.shared.b16 {%0,%1,%2,%3}, [%4];"
                 : "=r"(r[0]), "=r"(r[1]), "=r"(r[2]), "=r"(r[3]) : "r"(a));
}
__device__ __forceinline__ void ldm_x2(uint32_t a, uint32_t* r) {
    asm volatile("ldmatrix.sync.aligned.m8n8.x2.shared.b16 {%0,%1}, [%2];"
                 : "=r"(r[0]), "=r"(r[1]) : "r"(a));
}
__device__ __forceinline__ void ldm_x2t(uint32_t a, uint32_t* r) {
    asm volatile("ldmatrix.sync.aligned.m8n8.x2.trans.shared.b16 {%0,%1}, [%2];"
                 : "=r"(r[0]), "=r"(r[1]) : "r"(a));
}
__device__ __forceinline__ void mma_bf16(float* d, const uint32_t* a,
                                         const uint32_t* b) {
    asm volatile(
        "mma.sync.aligned.m16n8k16.row.col.f32.bf16.bf16.f32 "
        "{%0,%1,%2,%3}, {%4,%5,%6,%7}, {%8,%9}, {%0,%1,%2,%3};"
        : "+f"(d[0]), "+f"(d[1]), "+f"(d[2]), "+f"(d[3])
        : "r"(a[0]), "r"(a[1]), "r"(a[2]), "r"(a[3]), "r"(b[0]), "r"(b[1]));
}
__device__ __forceinline__ void mma_f16(float* d, const uint32_t* a,
                                        const uint32_t* b) {
    asm volatile(
        "mma.sync.aligned.m16n8k16.row.col.f32.f16.f16.f32 "
        "{%0,%1,%2,%3}, {%4,%5,%6,%7}, {%8,%9}, {%0,%1,%2,%3};"
        : "+f"(d[0]), "+f"(d[1]), "+f"(d[2]), "+f"(d[3])
        : "r"(a[0]), "r"(a[1]), "r"(a[2]), "r"(a[3]), "r"(b[0]), "r"(b[1]));
}
__device__ __forceinline__ void cpa16(uint32_t dst, const void* src) {
    asm volatile("cp.async.cg.shared.global [%0], [%1], 16;"
                 :: "r"(dst), "l"(src));
}
__device__ __forceinline__ void cpa_commit() {
    asm volatile("cp.async.commit_group;" ::: "memory");
}
__device__ __forceinline__ void cpa_wait0() {
    asm volatile("cp.async.wait_group 0;" ::: "memory");
}
constexpr float L2E = 1.4426950408889634f;
} // namespace

// ------- prepass: fp32 K -> bf16 hi/lo, fp32 V -> fp16 hi/lo scratch --------
__global__ void __launch_bounds__(256, 8)
conv_kv_kernel(const float* __restrict__ K, const float* __restrict__ V)
{
    const size_t i4 = (size_t)blockIdx.x * 256 + threadIdx.x;
    const float4 kv = *(const float4*)(K + i4 * 4);
    const float4 vv = *(const float4*)(V + i4 * 4);
    const float khx = bfr(kv.x), khy = bfr(kv.y), khz = bfr(kv.z), khw = bfr(kv.w);
    const float vhx = hfr(vv.x), vhy = hfr(vv.y), vhz = hfr(vv.z), vhw = hfr(vv.w);
    ((uint2*)g_KH)[i4] = make_uint2(pack2(kv.x, kv.y), pack2(kv.z, kv.w));
    ((uint2*)g_KL)[i4] =
        make_uint2(pack2(kv.x - khx, kv.y - khy), pack2(kv.z - khz, kv.w - khw));
    ((uint2*)g_VH)[i4] = make_uint2(packh2(vv.x, vv.y), packh2(vv.z, vv.w));
    ((uint2*)g_VL)[i4] =
        make_uint2(packh2(vv.x - vhx, vv.y - vhy), packh2(vv.z - vhz, vv.w - vhw));
}

// ---------------------------- main kernel -----------------------------------
__global__ void __launch_bounds__(NT, 2)
attn_mma_kernel(const float* __restrict__ Q, const float* __restrict__ Mk,
                float* __restrict__ OC)
{
    extern __shared__ char smem[];
    const uint32_t sb = smem_u32(smem);

    const int t = threadIdx.x, w = t >> 5, l = t & 31;
    const int qw = w & 3, kh = w >> 2;
    const int gid = l >> 2, qd = l & 3;
    const int qt = blockIdx.x, bh = blockIdx.y;

    const float* Qb = Q + ((long)bh * Sd + qt * QT) * Dd;
    const float* Mb = Mk + ((long)bh * Sd + qt * QT) * Sd;
    float*       Cb = OC + ((long)bh * Sd + qt * QT) * Dd;

    const __nv_bfloat16* KHb = g_KH + (long)bh * Sd * Dd;
    const __nv_bfloat16* KLb = g_KL + (long)bh * Sd * Dd;
    const __half*        VHb = g_VH + (long)bh * Sd * Dd;
    const __half*        VLb = g_VL + (long)bh * Sd * Dd;

    auto stage = [&](int c, int buf) {
        const long srow = (long)c * CH * Dd;
        const uint32_t kb = sb + SK + buf * 2 * TILE;
        const uint32_t vb = sb + SV + buf * 2 * TILE;
        #pragma unroll
        for (int half = 0; half < 2; ++half) {
            const int g = t + half * 256;
            const int r = g >> 3, u = g & 7;
            const long so = srow + r * Dd + u * 8;
            const uint32_t dofs = (uint32_t)((r * PIT + u * 8) * 2);
            cpa16(kb + dofs, KHb + so);
            cpa16(kb + TILE + dofs, KLb + so);
            cpa16(vb + dofs, VHb + so);
            cpa16(vb + TILE + dofs, VLb + so);
        }
    };

    stage(0, 0);
    cpa_commit();
    // Q convert (x 1/8 x log2(e)), into the (currently free) K buf-1 region.
    #pragma unroll
    for (int i = 0; i < 4; ++i) {
        const int idx4 = t + NT * i;
        const int row = idx4 >> 4, c4 = (idx4 & 15) << 2;
        float4 v = *(const float4*)(Qb + (size_t)idx4 * 4);
        const float qs = 0.125f * L2E;
        v.x *= qs; v.y *= qs; v.z *= qs; v.w *= qs;
        const float hx = bfr(v.x), hy = bfr(v.y), hz = bfr(v.z), hw = bfr(v.w);
        const int boff = (row * PIT + c4) * 2;
        *(uint2*)(smem + SQH + boff) = make_uint2(pack2(v.x, v.y), pack2(v.z, v.w));
        *(uint2*)(smem + SQL + boff) =
            make_uint2(pack2(v.x - hx, v.y - hy), pack2(v.z - hz, v.w - hw));
    }
    __syncthreads();

    uint32_t qh[4][4], ql[4][4];
    {
        const int rowb = ((16 * qw + (l & 15)) * PIT + ((l >> 4) << 3)) * 2;
        #pragma unroll
        for (int kt = 0; kt < 4; ++kt) {
            ldm_x4(sb + SQH + rowb + kt * 32, qh[kt]);
            ldm_x4(sb + SQL + rowb + kt * 32, ql[kt]);
        }
    }
    cpa_wait0();
    __syncthreads();   // Q frags in regs; buf-1 region may now be overwritten

    float ctx[8][4];
    #pragma unroll
    for (int d = 0; d < 8; ++d)
        { ctx[d][0] = 0.f; ctx[d][1] = 0.f; ctx[d][2] = 0.f; ctx[d][3] = 0.f; }
    float rs0 = 0.f, rs1 = 0.f;

    const int l2 = l & 15;
    const int koff = ((l2 & 7) * PIT + ((l2 >> 3) << 3)) * 2;
    const int voff = (l2 * PIT) * 2;

    const float* mrow = Mb + (long)(16 * qw + gid) * Sd + kh * 32 + 2 * qd;

    // fp16 attention plane, u32 granules (2 cols each).
    uint32_t* PfU = (uint32_t*)g_Pf;
    const size_t prow0 =
        ((size_t)bh * Sd + qt * QT + 16 * qw + gid) * (Sd / 2) + kh * 16 + qd;
    const size_t prow8 = prow0 + 8 * (size_t)(Sd / 2);

    // Mask pipeline: chunk-0 mask loaded up front.
    float2 mk0[4], mk1[4];
    #pragma unroll
    for (int nt = 0; nt < 4; ++nt) {
        mk0[nt] = *(const float2*)(mrow + nt * 8);
        mk1[nt] = *(const float2*)(mrow + nt * 8 + 8 * (long)Sd);
    }

    for (int c = 0; c < NCH; ++c) {
        const int buf = c & 1;
        if (c + 1 < NCH) { stage(c + 1, buf ^ 1); cpa_commit(); }

        const uint32_t kh_base = sb + SK + buf * 2 * TILE + koff;
        const uint32_t kl_base = kh_base + TILE;
        const uint32_t vh_base = sb + SV + buf * 2 * TILE + voff;
        const uint32_t vl_base = vh_base + TILE;

        uint32_t Ph[8];   // fp16 P fragments (also the stored attn values)
        #pragma unroll
        for (int nt = 0; nt < 4; ++nt) {
            const int ntg = kh * 4 + nt;
            float sA[4] = {0.f,0.f,0.f,0.f};
            float sB[4] = {0.f,0.f,0.f,0.f};
            float sC[4] = {0.f,0.f,0.f,0.f};
            #pragma unroll
            for (int kt = 0; kt < 4; ++kt) {
                const uint32_t off = (uint32_t)(ntg * 8 * PIT * 2 + kt * 32);
                uint32_t kfh[2], kfl[2];
                ldm_x2(kh_base + off, kfh);
                ldm_x2(kl_base + off, kfl);
                mma_bf16(sA, qh[kt], kfh);
                mma_bf16(sB, qh[kt], kfl);
                mma_bf16(sC, ql[kt], kfh);
            }
            // e = 2^(s + m*log2e); Q already carries the log2e factor.
            const float e0 = exp2f(fmaf(mk0[nt].x, L2E, (sA[0] + sB[0]) + sC[0]));
            const float e1 = exp2f(fmaf(mk0[nt].y, L2E, (sA[1] + sB[1]) + sC[1]));
            const float e2 = exp2f(fmaf(mk1[nt].x, L2E, (sA[2] + sB[2]) + sC[2]));
            const float e3 = exp2f(fmaf(mk1[nt].y, L2E, (sA[3] + sB[3]) + sC[3]));
            rs0 += e0 + e1; rs1 += e2 + e3;
            Ph[2 * nt]     = packh2(e0, e1);
            Ph[2 * nt + 1] = packh2(e2, e3);
            // fp16 attention store: one u32 per (row, 2-col) pair.
            const size_t ci = (size_t)c * 32 + nt * 4;
            PfU[prow0 + ci] = Ph[2 * nt];
            PfU[prow8 + ci] = Ph[2 * nt + 1];
        }

        // Prefetch next chunk's mask (mk regs dead; lands ~PV-phase ahead of use).
        if (c + 1 < NCH) {
            const int cn = (c + 1) * CH;
            #pragma unroll
            for (int nt = 0; nt < 4; ++nt) {
                mk0[nt] = *(const float2*)(mrow + cn + nt * 8);
                mk1[nt] = *(const float2*)(mrow + cn + nt * 8 + 8 * (long)Sd);
            }
        }

        // PV: fp16 P x fp16 (Vh + Vl) = 2 MMAs per (kt, dt).
        #pragma unroll
        for (int kt = 0; kt < 2; ++kt) {
            const int ktg = kh * 2 + kt;
            const uint32_t* ah = Ph + 4 * kt;
            const uint32_t vrow = (uint32_t)(ktg * 16 * PIT * 2);
            #pragma unroll
            for (int dt = 0; dt < 8; ++dt) {
                uint32_t vfh[2], vfl[2];
                ldm_x2t(vh_base + vrow + dt * 16, vfh);
                ldm_x2t(vl_base + vrow + dt * 16, vfl);
                mma_f16(ctx[dt], ah, vfh);
                mma_f16(ctx[dt], ah, vfl);
            }
        }
        if (c + 1 < NCH) cpa_wait0();
        __syncthreads();
    }

    // rowsum: quad-reduce, then combine the two k-halves through smem.
    #pragma unroll
    for (int o = 1; o < 4; o <<= 1) {
        rs0 += __shfl_xor_sync(0xffffffffu, rs0, o);
        rs1 += __shfl_xor_sync(0xffffffffu, rs1, o);
    }
    float* srs = (float*)smem;            // [2][64]
    if (qd == 0) {
        srs[kh * 64 + 16 * qw + gid]     = rs0;
        srs[kh * 64 + 16 * qw + gid + 8] = rs1;
    }
    __syncthreads();
    const int r0 = 16 * qw + gid;
    const float inv0 = 1.0f / (srs[r0] + srs[64 + r0]);
    const float inv1 = 1.0f / (srs[r0 + 8] + srs[64 + r0 + 8]);
    if (qd == 0 && kh == 0) {
        const int grow = bh * Sd + qt * QT + r0;
        g_inv[grow]     = inv0;
        g_inv[grow + 8] = inv1;
    }

    // ctx: half 1 publishes partials (pitch-68), half 0 adds + stores.
    float* cs = (float*)(smem + 1024);    // 64 x 68 floats
    if (kh == 1) {
        #pragma unroll
        for (int dt = 0; dt < 8; ++dt) {
            *(float2*)(cs + r0 * 68 + dt * 8 + 2 * qd) =
                make_float2(ctx[dt][0], ctx[dt][1]);
            *(float2*)(cs + (r0 + 8) * 68 + dt * 8 + 2 * qd) =
                make_float2(ctx[dt][2], ctx[dt][3]);
        }
    }
    __syncthreads();
    if (kh == 0) {
        float* crow = Cb + (long)r0 * Dd + 2 * qd;
        #pragma unroll
        for (int dt = 0; dt < 8; ++dt) {
            const float2 p0 = *(const float2*)(cs + r0 * 68 + dt * 8 + 2 * qd);
            const float2 p1 = *(const float2*)(cs + (r0 + 8) * 68 + dt * 8 + 2 * qd);
            *(float2*)(crow + dt * 8) =
                make_float2((ctx[dt][0] + p0.x) * inv0, (ctx[dt][1] + p0.y) * inv0);
            *(float2*)(crow + dt * 8 + 8 * Dd) =
                make_float2((ctx[dt][2] + p1.x) * inv1, (ctx[dt][3] + p1.y) * inv1);
        }
    }
}

// ---------- norm: fp16 unnormalized attn -> fp32 normalized attn ------------
__global__ void __launch_bounds__(256, 8)
attn_norm_kernel(float* __restrict__ A)
{
    const size_t i = (size_t)blockIdx.x * 256 + threadIdx.x;  // uint4 = 8 cols
    const uint4 u = ((const uint4*)g_Pf)[i];
    const size_t col0 = i * 8;
    const float s = g_inv[col0 >> 11];
    const float2 f0 = __half22float2(*(const __half2*)&u.x);
    const float2 f1 = __half22float2(*(const __half2*)&u.y);
    const float2 f2 = __half22float2(*(const __half2*)&u.z);
    const float2 f3 = __half22float2(*(const __half2*)&u.w);
    float4 o0, o1;
    o0.x = f0.x * s; o0.y = f0.y * s; o0.z = f1.x * s; o0.w = f1.y * s;
    o1.x = f2.x * s; o1.y = f2.y * s; o1.z = f3.x * s; o1.w = f3.y * s;
    *(float4*)(A + col0) = o0;
    *(float4*)(A + col0 + 4) = o1;
}

extern "C" void kernel_launch(void* const* d_in, const int* in_sizes, int n_in,
                              void* d_out, int out_size) {
    const float* Q = (const float*)d_in[0];
    const float* K = (const float*)d_in[1];
    const float* V = (const float*)d_in[2];
    const float* M = (const float*)d_in[3];

    float* ctx  = (float*)d_out;
    float* attn = (float*)d_out + (size_t)2 * 16 * 2048 * 64;

    cudaFuncSetAttribute(attn_mma_kernel,
                         cudaFuncAttributeMaxDynamicSharedMemorySize, SMEM_BYTES);

    conv_kv_kernel<<<4096, 256>>>(K, V);

    dim3 grid(Sd / QT, 32);   // (32, 32)
    attn_mma_kernel<<<grid, NT, SMEM_BYTES>>>(Q, M, ctx);

    const size_t total8 = (size_t)32 * 2048 * 2048 / 8;   // 8 cols per thread
    attn_norm_kernel<<<(unsigned)(total8 / 256), 256>>>(attn);
}

// round 17
// speedup vs baseline: 1.4961x; 1.2249x over previous
#include <cuda_runtime.h>
#include <cuda_fp16.h>
#include <cstdint>

namespace {
constexpr int Sd = 2048, Dd = 64, QT = 64, CH = 64, NCH = Sd / CH, NT = 256;
constexpr int PIT = 72;                      // 16-bit row pitch (conflict-free LDSM)
constexpr int TILE = QT * PIT * 2;           // 9216 bytes per tile
// K: 2 bufs x (hi+lo); Q (single fp16 tile) overlaid on K buf 1; V: 2 bufs x hi.
constexpr int SK  = 0;
constexpr int SQ  = SK + 2 * TILE;
constexpr int SV  = 4 * TILE;
constexpr int SMEM_BYTES = 6 * TILE + 256;   // 55552

__device__ float g_inv[65536];
__device__ __half g_KH[2 * 16 * 2048 * 64];  // fp16 K hi
__device__ __half g_KL[2 * 16 * 2048 * 64];  // fp16 K residual
__device__ __half g_VH[2 * 16 * 2048 * 64];  // fp16 V
// fp16 unnormalized attention intermediate (268 MB).
__device__ __half g_Pf[(size_t)32 * 2048 * 2048];

__device__ __forceinline__ uint32_t smem_u32(const void* p) {
    uint32_t a;
    asm("{ .reg .u64 t; cvta.to.shared.u64 t, %1; cvt.u32.u64 %0, t; }"
        : "=r"(a) : "l"(p));
    return a;
}
__device__ __forceinline__ uint32_t packh2(float a, float b) { // fp16: lo=a, hi=b
    uint32_t r;
    asm("cvt.rn.f16x2.f32 %0, %1, %2;" : "=r"(r) : "f"(b), "f"(a));
    return r;
}
__device__ __forceinline__ float hfr(float x) {
    return __half2float(__float2half_rn(x));
}
__device__ __forceinline__ void ldm_x4(uint32_t a, uint32_t* r) {
    asm volatile("ldmatrix.sync.aligned.m8n8.x4.shared.b16 {%0,%1,%2,%3}, [%4];"
                 : "=r"(r[0]), "=r"(r[1]), "=r"(r[2]), "=r"(r[3]) : "r"(a));
}
__device__ __forceinline__ void ldm_x2(uint32_t a, uint32_t* r) {
    asm volatile("ldmatrix.sync.aligned.m8n8.x2.shared.b16 {%0,%1}, [%2];"
                 : "=r"(r[0]), "=r"(r[1]) : "r"(a));
}
__device__ __forceinline__ void ldm_x2t(uint32_t a, uint32_t* r) {
    asm volatile("ldmatrix.sync.aligned.m8n8.x2.trans.shared.b16 {%0,%1}, [%2];"
                 : "=r"(r[0]), "=r"(r[1]) : "r"(a));
}
__device__ __forceinline__ void mma_f16(float* d, const uint32_t* a,
                                        const uint32_t* b) {
    asm volatile(
        "mma.sync.aligned.m16n8k16.row.col.f32.f16.f16.f32 "
        "{%0,%1,%2,%3}, {%4,%5,%6,%7}, {%8,%9}, {%0,%1,%2,%3};"
        : "+f"(d[0]), "+f"(d[1]), "+f"(d[2]), "+f"(d[3])
        : "r"(a[0]), "r"(a[1]), "r"(a[2]), "r"(a[3]), "r"(b[0]), "r"(b[1]));
}
__device__ __forceinline__ void cpa16(uint32_t dst, const void* src) {
    asm volatile("cp.async.cg.shared.global [%0], [%1], 16;"
                 :: "r"(dst), "l"(src));
}
__device__ __forceinline__ void cpa_commit() {
    asm volatile("cp.async.commit_group;" ::: "memory");
}
__device__ __forceinline__ void cpa_wait0() {
    asm volatile("cp.async.wait_group 0;" ::: "memory");
}
constexpr float L2E = 1.4426950408889634f;
} // namespace

// ------- prepass: fp32 K -> fp16 hi/lo, fp32 V -> fp16 scratch --------------
__global__ void __launch_bounds__(256, 8)
conv_kv_kernel(const float* __restrict__ K, const float* __restrict__ V)
{
    const size_t i4 = (size_t)blockIdx.x * 256 + threadIdx.x;
    const float4 kv = *(const float4*)(K + i4 * 4);
    const float4 vv = *(const float4*)(V + i4 * 4);
    const float khx = hfr(kv.x), khy = hfr(kv.y), khz = hfr(kv.z), khw = hfr(kv.w);
    ((uint2*)g_KH)[i4] = make_uint2(packh2(kv.x, kv.y), packh2(kv.z, kv.w));
    ((uint2*)g_KL)[i4] =
        make_uint2(packh2(kv.x - khx, kv.y - khy), packh2(kv.z - khz, kv.w - khw));
    ((uint2*)g_VH)[i4] = make_uint2(packh2(vv.x, vv.y), packh2(vv.z, vv.w));
}

// ---------------------------- main kernel -----------------------------------
__global__ void __launch_bounds__(NT, 2)
attn_mma_kernel(const float* __restrict__ Q, const float* __restrict__ Mk,
                float* __restrict__ OC)
{
    extern __shared__ char smem[];
    const uint32_t sb = smem_u32(smem);

    const int t = threadIdx.x, w = t >> 5, l = t & 31;
    const int qw = w & 3, kh = w >> 2;
    const int gid = l >> 2, qd = l & 3;
    const int qt = blockIdx.x, bh = blockIdx.y;

    const float* Qb = Q + ((long)bh * Sd + qt * QT) * Dd;
    const float* Mb = Mk + ((long)bh * Sd + qt * QT) * Sd;
    float*       Cb = OC + ((long)bh * Sd + qt * QT) * Dd;

    const __half* KHb = g_KH + (long)bh * Sd * Dd;
    const __half* KLb = g_KL + (long)bh * Sd * Dd;
    const __half* VHb = g_VH + (long)bh * Sd * Dd;

    auto stage = [&](int c, int buf) {
        const long srow = (long)c * CH * Dd;
        const uint32_t kb = sb + SK + buf * 2 * TILE;
        const uint32_t vb = sb + SV + buf * TILE;
        #pragma unroll
        for (int half = 0; half < 2; ++half) {
            const int g = t + half * 256;
            const int r = g >> 3, u = g & 7;
            const long so = srow + r * Dd + u * 8;
            const uint32_t dofs = (uint32_t)((r * PIT + u * 8) * 2);
            cpa16(kb + dofs, KHb + so);
            cpa16(kb + TILE + dofs, KLb + so);
            cpa16(vb + dofs, VHb + so);
        }
    };

    stage(0, 0);
    cpa_commit();
    // Q convert (x 1/8 x log2(e)) -> single fp16 tile in K buf-1 region.
    #pragma unroll
    for (int i = 0; i < 4; ++i) {
        const int idx4 = t + NT * i;
        const int row = idx4 >> 4, c4 = (idx4 & 15) << 2;
        float4 v = *(const float4*)(Qb + (size_t)idx4 * 4);
        const float qs = 0.125f * L2E;
        v.x *= qs; v.y *= qs; v.z *= qs; v.w *= qs;
        const int boff = (row * PIT + c4) * 2;
        *(uint2*)(smem + SQ + boff) = make_uint2(packh2(v.x, v.y), packh2(v.z, v.w));
    }
    __syncthreads();

    uint32_t qf[4][4];
    {
        const int rowb = ((16 * qw + (l & 15)) * PIT + ((l >> 4) << 3)) * 2;
        #pragma unroll
        for (int kt = 0; kt < 4; ++kt)
            ldm_x4(sb + SQ + rowb + kt * 32, qf[kt]);
    }
    cpa_wait0();
    __syncthreads();   // Q frags in regs; buf-1 region may now be overwritten

    float ctx[8][4];
    #pragma unroll
    for (int d = 0; d < 8; ++d)
        { ctx[d][0] = 0.f; ctx[d][1] = 0.f; ctx[d][2] = 0.f; ctx[d][3] = 0.f; }
    float rs0 = 0.f, rs1 = 0.f;

    const int l2 = l & 15;
    const int koff = ((l2 & 7) * PIT + ((l2 >> 3) << 3)) * 2;
    const int voff = (l2 * PIT) * 2;

    const float* mrow = Mb + (long)(16 * qw + gid) * Sd + kh * 32 + 2 * qd;

    // fp16 attention plane, u32 granules (2 cols each).
    uint32_t* PfU = (uint32_t*)g_Pf;
    const size_t prow0 =
        ((size_t)bh * Sd + qt * QT + 16 * qw + gid) * (Sd / 2) + kh * 16 + qd;
    const size_t prow8 = prow0 + 8 * (size_t)(Sd / 2);

    // Mask pipeline: chunk-0 mask loaded up front.
    float2 mk0[4], mk1[4];
    #pragma unroll
    for (int nt = 0; nt < 4; ++nt) {
        mk0[nt] = *(const float2*)(mrow + nt * 8);
        mk1[nt] = *(const float2*)(mrow + nt * 8 + 8 * (long)Sd);
    }

    for (int c = 0; c < NCH; ++c) {
        const int buf = c & 1;
        if (c + 1 < NCH) { stage(c + 1, buf ^ 1); cpa_commit(); }

        const uint32_t kh_base = sb + SK + buf * 2 * TILE + koff;
        const uint32_t kl_base = kh_base + TILE;
        const uint32_t vh_base = sb + SV + buf * TILE + voff;

        uint32_t Ph[8];   // fp16 P fragments (also the stored attn values)
        #pragma unroll
        for (int nt = 0; nt < 4; ++nt) {
            const int ntg = kh * 4 + nt;
            float sA[4] = {0.f,0.f,0.f,0.f};
            float sB[4] = {0.f,0.f,0.f,0.f};
            #pragma unroll
            for (int kt = 0; kt < 4; ++kt) {
                const uint32_t off = (uint32_t)(ntg * 8 * PIT * 2 + kt * 32);
                uint32_t kfh[2], kfl[2];
                ldm_x2(kh_base + off, kfh);
                ldm_x2(kl_base + off, kfl);
                mma_f16(sA, qf[kt], kfh);
                mma_f16(sB, qf[kt], kfl);
            }
            // e = 2^(s + m*log2e); Q already carries the log2e factor.
            const float e0 = exp2f(fmaf(mk0[nt].x, L2E, sA[0] + sB[0]));
            const float e1 = exp2f(fmaf(mk0[nt].y, L2E, sA[1] + sB[1]));
            const float e2 = exp2f(fmaf(mk1[nt].x, L2E, sA[2] + sB[2]));
            const float e3 = exp2f(fmaf(mk1[nt].y, L2E, sA[3] + sB[3]));
            rs0 += e0 + e1; rs1 += e2 + e3;
            Ph[2 * nt]     = packh2(e0, e1);
            Ph[2 * nt + 1] = packh2(e2, e3);
            // fp16 attention store: one u32 per (row, 2-col) pair.
            const size_t ci = (size_t)c * 32 + nt * 4;
            PfU[prow0 + ci] = Ph[2 * nt];
            PfU[prow8 + ci] = Ph[2 * nt + 1];
        }

        // Prefetch next chunk's mask (mk regs dead; lands ~PV-phase ahead of use).
        if (c + 1 < NCH) {
            const int cn = (c + 1) * CH;
            #pragma unroll
            for (int nt = 0; nt < 4; ++nt) {
                mk0[nt] = *(const float2*)(mrow + cn + nt * 8);
                mk1[nt] = *(const float2*)(mrow + cn + nt * 8 + 8 * (long)Sd);
            }
        }

        // PV: fp16 P x fp16 V = 1 MMA per (kt, dt).
        #pragma unroll
        for (int kt = 0; kt < 2; ++kt) {
            const int ktg = kh * 2 + kt;
            const uint32_t* ah = Ph + 4 * kt;
            const uint32_t vrow = (uint32_t)(ktg * 16 * PIT * 2);
            #pragma unroll
            for (int dt = 0; dt < 8; ++dt) {
                uint32_t vfh[2];
                ldm_x2t(vh_base + vrow + dt * 16, vfh);
                mma_f16(ctx[dt], ah, vfh);
            }
        }
        if (c + 1 < NCH) cpa_wait0();
        __syncthreads();
    }

    // rowsum: quad-reduce, then combine the two k-halves through smem.
    #pragma unroll
    for (int o = 1; o < 4; o <<= 1) {
        rs0 += __shfl_xor_sync(0xffffffffu, rs0, o);
        rs1 += __shfl_xor_sync(0xffffffffu, rs1, o);
    }
    float* srs = (float*)smem;            // [2][64]
    if (qd == 0) {
        srs[kh * 64 + 16 * qw + gid]     = rs0;
        srs[kh * 64 + 16 * qw + gid + 8] = rs1;
    }
    __syncthreads();
    const int r0 = 16 * qw + gid;
    const float inv0 = 1.0f / (srs[r0] + srs[64 + r0]);
    const float inv1 = 1.0f / (srs[r0 + 8] + srs[64 + r0 + 8]);
    if (qd == 0 && kh == 0) {
        const int grow = bh * Sd + qt * QT + r0;
        g_inv[grow]     = inv0;
        g_inv[grow + 8] = inv1;
    }

    // ctx: half 1 publishes partials (pitch-68), half 0 adds + stores.
    float* cs = (float*)(smem + 1024);    // 64 x 68 floats
    if (kh == 1) {
        #pragma unroll
        for (int dt = 0; dt < 8; ++dt) {
            *(float2*)(cs + r0 * 68 + dt * 8 + 2 * qd) =
                make_float2(ctx[dt][0], ctx[dt][1]);
            *(float2*)(cs + (r0 + 8) * 68 + dt * 8 + 2 * qd) =
                make_float2(ctx[dt][2], ctx[dt][3]);
        }
    }
    __syncthreads();
    if (kh == 0) {
        float* crow = Cb + (long)r0 * Dd + 2 * qd;
        #pragma unroll
        for (int dt = 0; dt < 8; ++dt) {
            const float2 p0 = *(const float2*)(cs + r0 * 68 + dt * 8 + 2 * qd);
            const float2 p1 = *(const float2*)(cs + (r0 + 8) * 68 + dt * 8 + 2 * qd);
            *(float2*)(crow + dt * 8) =
                make_float2((ctx[dt][0] + p0.x) * inv0, (ctx[dt][1] + p0.y) * inv0);
            *(float2*)(crow + dt * 8 + 8 * Dd) =
                make_float2((ctx[dt][2] + p1.x) * inv1, (ctx[dt][3] + p1.y) * inv1);
        }
    }
}

// ---------- norm: fp16 unnormalized attn -> fp32 normalized attn ------------
__global__ void __launch_bounds__(256, 8)
attn_norm_kernel(float* __restrict__ A)
{
    const size_t i = (size_t)blockIdx.x * 256 + threadIdx.x;  // uint4 = 8 cols
    const uint4 u = ((const uint4*)g_Pf)[i];
    const size_t col0 = i * 8;
    const float s = g_inv[col0 >> 11];
    const float2 f0 = __half22float2(*(const __half2*)&u.x);
    const float2 f1 = __half22float2(*(const __half2*)&u.y);
    const float2 f2 = __half22float2(*(const __half2*)&u.z);
    const float2 f3 = __half22float2(*(const __half2*)&u.w);
    float4 o0, o1;
    o0.x = f0.x * s; o0.y = f0.y * s; o0.z = f1.x * s; o0.w = f1.y * s;
    o1.x = f2.x * s; o1.y = f2.y * s; o1.z = f3.x * s; o1.w = f3.y * s;
    *(float4*)(A + col0) = o0;
    *(float4*)(A + col0 + 4) = o1;
}

extern "C" void kernel_launch(void* const* d_in, const int* in_sizes, int n_in,
                              void* d_out, int out_size) {
    const float* Q = (const float*)d_in[0];
    const float* K = (const float*)d_in[1];
    const float* V = (const float*)d_in[2];
    const float* M = (const float*)d_in[3];

    float* ctx  = (float*)d_out;
    float* attn = (float*)d_out + (size_t)2 * 16 * 2048 * 64;

    cudaFuncSetAttribute(attn_mma_kernel,
                         cudaFuncAttributeMaxDynamicSharedMemorySize, SMEM_BYTES);

    conv_kv_kernel<<<4096, 256>>>(K, V);

    dim3 grid(Sd / QT, 32);   // (32, 32)
    attn_mma_kernel<<<grid, NT, SMEM_BYTES>>>(Q, M, ctx);

    const size_t total8 = (size_t)32 * 2048 * 2048 / 8;   // 8 cols per thread
    attn_norm_kernel<<<(unsigned)(total8 / 256), 256>>>(attn);
}